// round 1
// baseline (speedup 1.0000x reference)
#include <cuda_runtime.h>
#include <math.h>

#define B_ 8
#define T_ 1024
#define C_ 32
#define F_ 256
#define D_ 128
#define K_ 512
#define Q_ (B_*T_)      // 8192
#define KC 64
#define NKC (K_/KC)     // 8
#define QT 32
#define NQT (Q_/QT)     // 256

// ---------------- scratch (no allocations allowed) ----------------
__device__ float g_bd[NKC*Q_];
__device__ int   g_bi[NKC*Q_];
__device__ float g_E[Q_*C_];
__device__ float g_G[C_*F_];
__device__ float g_S[F_];
__device__ float g_acc[2];   // [0] = sum E^2, [1] = sum (h-z)^2

// ---------------- zero accumulators ----------------
__global__ void zero_kernel() {
    int tid = threadIdx.x;
    for (int i = tid; i < C_*F_; i += 256) g_G[i] = 0.f;
    if (tid < F_) g_S[tid] = 0.f;
    if (tid < 2)  g_acc[tid] = 0.f;
}

// ---------------- L1 NN search: tiled distance + running lexmin ----------------
// CTA = (32 queries) x (64 codewords), full D=128 depth.
__global__ void nn_kernel(const float* __restrict__ H, const float* __restrict__ M) {
    __shared__ float h_s[D_][QT];   // 16 KB
    __shared__ float m_s[D_][KC];   // 32 KB
    int qt = blockIdx.x & (NQT - 1);
    int kc = blockIdx.x >> 8;
    int q0 = qt * QT;
    int b  = q0 >> 10;
    int t0 = q0 & (T_ - 1);
    int k0 = kc * KC;
    int tid = threadIdx.x;

    for (int e = tid; e < D_*QT; e += 256) {
        int d = e >> 5, q = e & 31;
        h_s[d][q] = H[b*(D_*T_) + d*T_ + t0 + q];
    }
    for (int e = tid; e < D_*KC; e += 256) {
        int d = e >> 6, k = e & 63;
        m_s[d][k] = M[d*K_ + k0 + k];
    }
    __syncthreads();

    int tk = tid & 15, tq = tid >> 4;   // 16 k-groups x 16 q-groups
    int qq = tq * 2, kk = tk * 4;

    float d00=0.f,d01=0.f,d02=0.f,d03=0.f,d10=0.f,d11=0.f,d12=0.f,d13=0.f;
    #pragma unroll 4
    for (int d = 0; d < D_; d++) {
        float2 hv = *(const float2*)&h_s[d][qq];
        float4 mv = *(const float4*)&m_s[d][kk];
        d00 += fabsf(hv.x - mv.x); d01 += fabsf(hv.x - mv.y);
        d02 += fabsf(hv.x - mv.z); d03 += fabsf(hv.x - mv.w);
        d10 += fabsf(hv.y - mv.x); d11 += fabsf(hv.y - mv.y);
        d12 += fabsf(hv.y - mv.z); d13 += fabsf(hv.y - mv.w);
    }
    // thread-local lexmin (k ascending, strict < keeps lowest index)
    float bd0 = d00; int bi0 = k0 + kk;
    if (d01 < bd0) { bd0 = d01; bi0 = k0 + kk + 1; }
    if (d02 < bd0) { bd0 = d02; bi0 = k0 + kk + 2; }
    if (d03 < bd0) { bd0 = d03; bi0 = k0 + kk + 3; }
    float bd1 = d10; int bi1 = k0 + kk;
    if (d11 < bd1) { bd1 = d11; bi1 = k0 + kk + 1; }
    if (d12 < bd1) { bd1 = d12; bi1 = k0 + kk + 2; }
    if (d13 < bd1) { bd1 = d13; bi1 = k0 + kk + 3; }
    // reduce across the 16 tk lanes (lexicographic min keeps first-argmin semantics)
    #pragma unroll
    for (int off = 1; off < 16; off <<= 1) {
        float od = __shfl_xor_sync(0xffffffffu, bd0, off);
        int   oi = __shfl_xor_sync(0xffffffffu, bi0, off);
        if (od < bd0 || (od == bd0 && oi < bi0)) { bd0 = od; bi0 = oi; }
        od = __shfl_xor_sync(0xffffffffu, bd1, off);
        oi = __shfl_xor_sync(0xffffffffu, bi1, off);
        if (od < bd1 || (od == bd1 && oi < bi1)) { bd1 = od; bi1 = oi; }
    }
    if (tk == 0) {
        g_bd[kc*Q_ + q0 + qq    ] = bd0;  g_bi[kc*Q_ + q0 + qq    ] = bi0;
        g_bd[kc*Q_ + q0 + qq + 1] = bd1;  g_bi[kc*Q_ + q0 + qq + 1] = bi1;
    }
}

// ---------------- combine K-chunks, compute sum (h - z)^2 ----------------
__global__ void nnred_kernel(const float* __restrict__ H, const float* __restrict__ M) {
    int tid = threadIdx.x;
    int q = blockIdx.x * 256 + tid;
    float bd = g_bd[q]; int bi = g_bi[q];
    #pragma unroll
    for (int c = 1; c < NKC; c++) {
        float dd = g_bd[c*Q_ + q]; int ii = g_bi[c*Q_ + q];
        if (dd < bd) { bd = dd; bi = ii; }   // chunks ascend in k: strict < keeps lowest index
    }
    int b = q >> 10, t = q & (T_ - 1);
    const float* h = H + b*(D_*T_) + t;
    float s = 0.f;
    #pragma unroll 8
    for (int d = 0; d < D_; d++) {
        float diff = h[d*T_] - M[d*K_ + bi];
        s += diff * diff;
    }
    #pragma unroll
    for (int off = 16; off > 0; off >>= 1) s += __shfl_down_sync(0xffffffffu, s, off);
    __shared__ float red[8];
    int warp = tid >> 5, lane = tid & 31;
    if (lane == 0) red[warp] = s;
    __syncthreads();
    if (tid == 0) {
        float tot = 0.f;
        #pragma unroll
        for (int i = 0; i < 8; i++) tot += red[i];
        atomicAdd(&g_acc[1], tot);
    }
}

// ---------------- E = Hdec @ W^T - X ; accumulate sum E^2 ----------------
__global__ void e_kernel(const float* __restrict__ Hdec, const float* __restrict__ W,
                         const float* __restrict__ X) {
    __shared__ float w_s[F_][C_ + 1];   // padded: conflict-free transpose
    __shared__ float hd_s[64][32];
    __shared__ float red[8];
    int tid = threadIdx.x;
    int r0 = blockIdx.x * 64;
    for (int e = tid; e < C_*F_; e += 256) {
        int c = e >> 8, f = e & 255;
        w_s[f][c] = W[c*F_ + f];
    }
    int warp = tid >> 5, lane = tid & 31;   // lane = output channel c
    float acc[8] = {0.f,0.f,0.f,0.f,0.f,0.f,0.f,0.f};
    for (int fc = 0; fc < 8; fc++) {
        __syncthreads();
        for (int e = tid; e < 64*32; e += 256) {
            int rr = e >> 5, j = e & 31;
            hd_s[rr][j] = Hdec[(r0 + rr)*F_ + fc*32 + j];
        }
        __syncthreads();
        #pragma unroll
        for (int jq = 0; jq < 32; jq += 4) {
            float w0 = w_s[fc*32 + jq + 0][lane];
            float w1 = w_s[fc*32 + jq + 1][lane];
            float w2 = w_s[fc*32 + jq + 2][lane];
            float w3 = w_s[fc*32 + jq + 3][lane];
            #pragma unroll
            for (int i = 0; i < 8; i++) {
                float4 h4 = *(const float4*)&hd_s[warp*8 + i][jq];
                acc[i] += h4.x*w0 + h4.y*w1 + h4.z*w2 + h4.w*w3;
            }
        }
    }
    float s2 = 0.f;
    #pragma unroll
    for (int i = 0; i < 8; i++) {
        int row = r0 + warp*8 + i;
        float ev = acc[i] - X[row*C_ + lane];
        g_E[row*C_ + lane] = ev;
        s2 += ev * ev;
    }
    #pragma unroll
    for (int off = 16; off > 0; off >>= 1) s2 += __shfl_down_sync(0xffffffffu, s2, off);
    if (lane == 0) red[warp] = s2;
    __syncthreads();
    if (tid == 0) {
        float tot = 0.f;
        #pragma unroll
        for (int i = 0; i < 8; i++) tot += red[i];
        atomicAdd(&g_acc[0], tot);
    }
}

// ---------------- G[c,f] = sum_r E[r,c] * Hdec[r,f] (partial-atomic) ----------------
__global__ void g_kernel(const float* __restrict__ Hdec) {
    __shared__ float e_s[32][32];
    __shared__ float hd_s[32][32];
    int tid = threadIdx.x;
    int ft = blockIdx.x & 7, rc = blockIdx.x >> 3;
    int f0 = ft * 32, r0 = rc * 1024;
    int c = tid >> 3, fg = tid & 7;
    float a0=0.f, a1=0.f, a2=0.f, a3=0.f;
    for (int rt = 0; rt < 1024; rt += 32) {
        __syncthreads();
        for (int e = tid; e < 1024; e += 256) {
            int rr = e >> 5, j = e & 31;
            e_s[rr][j]  = g_E[(r0 + rt + rr)*C_ + j];
            hd_s[rr][j] = Hdec[(r0 + rt + rr)*F_ + f0 + j];
        }
        __syncthreads();
        #pragma unroll 8
        for (int r = 0; r < 32; r++) {
            float ev = e_s[r][c];
            float4 h4 = *(const float4*)&hd_s[r][fg*4];
            a0 += ev*h4.x; a1 += ev*h4.y; a2 += ev*h4.z; a3 += ev*h4.w;
        }
    }
    atomicAdd(&g_G[c*F_ + f0 + fg*4 + 0], a0);
    atomicAdd(&g_G[c*F_ + f0 + fg*4 + 1], a1);
    atomicAdd(&g_G[c*F_ + f0 + fg*4 + 2], a2);
    atomicAdd(&g_G[c*F_ + f0 + fg*4 + 3], a3);
}

// ---------------- S[f] = sum over (b,t) of Hdec ----------------
__global__ void s_kernel(const float* __restrict__ Hdec) {
    int tid = threadIdx.x;        // tid == f
    int r0 = blockIdx.x * 128;
    float s = 0.f;
    for (int r = 0; r < 128; r++) s += Hdec[(r0 + r)*F_ + tid];
    atomicAdd(&g_S[tid], s);
}

// ---------------- final scalar assembly ----------------
__global__ void final_kernel(const float* __restrict__ W, const float* __restrict__ w_d,
                             float* __restrict__ out) {
    __shared__ float red[256];
    int tid = threadIdx.x;

    float s = 0.f;
    for (int i = tid; i < C_*F_; i += 256) { float v = g_G[i]; s += v*v; }
    red[tid] = s; __syncthreads();
    for (int o = 128; o > 0; o >>= 1) { if (tid < o) red[tid] += red[tid+o]; __syncthreads(); }
    float sumG2 = red[0]; __syncthreads();

    float sv = g_S[tid];
    red[tid] = sv * sv; __syncthreads();
    for (int o = 128; o > 0; o >>= 1) { if (tid < o) red[tid] += red[tid+o]; __syncthreads(); }
    float sumS2 = red[0]; __syncthreads();

    red[tid] = (tid < C_) ? w_d[tid]*w_d[tid] : 0.f; __syncthreads();
    for (int o = 128; o > 0; o >>= 1) { if (tid < o) red[tid] += red[tid+o]; __syncthreads(); }
    float sumwd2 = red[0]; __syncthreads();

    s = 0.f;
    for (int i = tid; i < C_*F_; i += 256) s += W[i] * g_S[i & 255] * w_d[i >> 8];
    red[tid] = s; __syncthreads();
    for (int o = 128; o > 0; o >>= 1) { if (tid < o) red[tid] += red[tid+o]; __syncthreads(); }
    float dotWS = red[0];

    if (tid == 0) {
        float loss_rec = g_acc[0] / 262144.f;                 // mean over B*T*C
        float loss_m   = 2.f * g_acc[1] / 1048576.f;          // 2*sum/(B*D*T)
        float normGrec = (2.f / 262144.f) * sqrtf(sumG2);     // ||g_rec||_F
        float normGd   = sqrtf(sumwd2) * sqrtf(sumS2) / 8192.f; // ||g_d||_F (rank-1)
        float lmbda    = normGrec / (normGd + 1e-6f);
        float loss_d   = -dotWS / 8192.f;
        out[0] = loss_rec + loss_m + lmbda * loss_d;
    }
}

extern "C" void kernel_launch(void* const* d_in, const int* in_sizes, int n_in,
                              void* d_out, int out_size) {
    const float* X    = (const float*)d_in[0];
    const float* H    = (const float*)d_in[1];
    const float* M    = (const float*)d_in[2];
    const float* Hdec = (const float*)d_in[3];
    const float* W    = (const float*)d_in[4];
    const float* w_d  = (const float*)d_in[5];
    float* out = (float*)d_out;
    (void)in_sizes; (void)n_in; (void)out_size;

    zero_kernel <<<1, 256>>>();
    nn_kernel   <<<NQT*NKC, 256>>>(H, M);      // 2048 CTAs: the hot kernel
    nnred_kernel<<<Q_/256, 256>>>(H, M);
    e_kernel    <<<Q_/64, 256>>>(Hdec, W, X);
    g_kernel    <<<64, 256>>>(Hdec);
    s_kernel    <<<64, 256>>>(Hdec);
    final_kernel<<<1, 256>>>(W, w_d, out);
}